// round 11
// baseline (speedup 1.0000x reference)
#include <cuda_runtime.h>
#include <cuda_bf16.h>

// SelfAttention3D — GroupNorm(8 groups) -> QKV proj -> 8-head attention
// (dhead=32, n=4096) -> out proj + residual.  b=1, c=256.
//
// Pipeline (4 launches, graph-capturable, scratch in __device__ globals):
//   1. gn_stats      : per-group mean / rsqrt(var+eps)
//   2. gemm<NORMB>   : qkv = w_qkv @ groupnorm(x) + b_qkv   -> g_qkv [768][4096]
//                      (normalization fused into the B-tile load)
//   3. attn          : flash-attention, f32x2 FFMA2 + packed exp2 -> g_ao
//   4. gemm+resid    : out = w_out @ ao + b_out + x         -> d_out

#define N_TOK 4096
#define C_DIM 256
#define INNER 256
#define HEADS 8
#define DHEAD 32

__device__ float g_qkv[3 * INNER * N_TOK];
__device__ float g_ao[INNER * N_TOK];
__device__ float g_stats[16];

typedef unsigned long long u64;

// ---------------------------------------------------------------------------
// Packed f32x2 helpers (sm_103a FFMA2 path — only reachable via PTX).
// ---------------------------------------------------------------------------
__device__ __forceinline__ u64 fma2(u64 a, u64 b, u64 c) {
    u64 d;
    asm("fma.rn.f32x2 %0, %1, %2, %3;" : "=l"(d) : "l"(a), "l"(b), "l"(c));
    return d;
}
__device__ __forceinline__ u64 add2(u64 a, u64 b) {
    u64 d;
    asm("add.rn.f32x2 %0, %1, %2;" : "=l"(d) : "l"(a), "l"(b));
    return d;
}
__device__ __forceinline__ u64 mul2(u64 a, u64 b) {
    u64 d;
    asm("mul.rn.f32x2 %0, %1, %2;" : "=l"(d) : "l"(a), "l"(b));
    return d;
}
__device__ __forceinline__ u64 pack2(float lo, float hi) {
    u64 d;
    unsigned l = __float_as_uint(lo), h = __float_as_uint(hi);
    asm("mov.b64 %0, {%1, %2};" : "=l"(d) : "r"(l), "r"(h));
    return d;
}
__device__ __forceinline__ float2 unpack2(u64 v) {
    unsigned l, h;
    asm("mov.b64 {%0, %1}, %2;" : "=r"(l), "=r"(h) : "l"(v));
    return make_float2(__uint_as_float(l), __uint_as_float(h));
}

// ---------------------------------------------------------------------------
// FFMA/ALU-only exp2 (scalar): magic-number round, degree-5 poly on [-.5,.5]
// (rel err ~2.4e-6), exponent splice via (bits(t)<<23). Keeps MUFU idle.
// ---------------------------------------------------------------------------
__device__ __forceinline__ float fast_exp2(float y) {
    y = fmaxf(y, -126.0f);
    float t = y + 12582912.0f;
    float f = y - (t - 12582912.0f);
    float p = 1.3333558146428443e-3f;
    p = fmaf(p, f, 9.6181291076284771e-3f);
    p = fmaf(p, f, 5.5504108664798463e-2f);
    p = fmaf(p, f, 2.4022650695910071e-1f);
    p = fmaf(p, f, 6.9314718055994531e-1f);
    p = fmaf(p, f, 1.0f);
    return __int_as_float(__float_as_int(p) + (__float_as_int(t) << 23));
}

// ---------------------------------------------------------------------------
// 1. GroupNorm statistics: one block per group (32 ch x 4096 elems)
// ---------------------------------------------------------------------------
__global__ __launch_bounds__(256) void gn_stats_kernel(
    const float* __restrict__ x, float* __restrict__ stats) {
    __shared__ float sh[512];
    const int g = blockIdx.x, tid = threadIdx.x;
    const float4* x4 = (const float4*)(x + g * 32 * N_TOK);
    float s = 0.f, s2 = 0.f;
    for (int i = tid; i < 32768; i += 256) {
        float4 v = x4[i];
        s  += (v.x + v.y) + (v.z + v.w);
        s2 += (v.x * v.x + v.y * v.y) + (v.z * v.z + v.w * v.w);
    }
    sh[tid] = s; sh[256 + tid] = s2;
    __syncthreads();
    for (int off = 128; off >= 32; off >>= 1) {
        if (tid < off) { sh[tid] += sh[tid + off]; sh[256 + tid] += sh[256 + tid + off]; }
        __syncthreads();
    }
    if (tid < 32) {                      // final 32 lanes: shuffle reduction
        float a = sh[tid], b = sh[256 + tid];
#pragma unroll
        for (int off = 16; off > 0; off >>= 1) {
            a += __shfl_down_sync(0xffffffffu, a, off);
            b += __shfl_down_sync(0xffffffffu, b, off);
        }
        if (tid == 0) {
            const float inv_n = 1.f / 131072.f;
            float mu  = a * inv_n;
            float var = b * inv_n - mu * mu;
            stats[2 * g]     = mu;
            stats[2 * g + 1] = rsqrtf(var + 1e-5f);
        }
    }
}

// ---------------------------------------------------------------------------
// 2/4. SGEMM, f32x2 inner loop: C[M,N] = A[M,K] @ B'[K,N] + bias[M] (+resid)
//      BM=BN=64, BK=16, 256 threads, 4x4 per-thread tile as 2x(2-row pairs).
//      NORMB: B' = groupnorm-affine applied to B during the tile load
//      (fuses gn_apply; B rows are channels). All dims divide exactly.
// ---------------------------------------------------------------------------
template <bool RESID, bool NORMB>
__global__ __launch_bounds__(256) void gemm_kernel(
    const float* __restrict__ A, const float* __restrict__ B,
    const float* __restrict__ bias, const float* __restrict__ resid,
    const float* __restrict__ gamma, const float* __restrict__ beta,
    const float* __restrict__ stats,
    float* __restrict__ C, int M, int N, int K) {
    // __align__(16): rows are 16B-multiples (272B / 256B) and the inner loop
    // issues LDS.128/STS.128 — base must be 16B-aligned (err715 otherwise).
    __shared__ __align__(16) float As[16][68];   // transposed A tile
    __shared__ __align__(16) float Bs[16][64];

    const int tid = threadIdx.x;
    const int m0 = blockIdx.y * 64;
    const int n0 = blockIdx.x * 64;
    const int ty = tid >> 4, tx = tid & 15;

    const int a_row = tid >> 2;
    const int a_k4  = tid & 3;
    const int b_k   = tid >> 4;
    const int b_j4  = tid & 15;

    u64 acc2[2][4];                // [row-pair][col]; rows ty*4+2*i2+{0,1}
#pragma unroll
    for (int i = 0; i < 2; i++)
#pragma unroll
        for (int j = 0; j < 4; j++) acc2[i][j] = 0ull;

    for (int k0 = 0; k0 < K; k0 += 16) {
        __syncthreads();
        float4 av = *(const float4*)&A[(m0 + a_row) * K + k0 + a_k4 * 4];
        As[a_k4 * 4 + 0][a_row] = av.x;
        As[a_k4 * 4 + 1][a_row] = av.y;
        As[a_k4 * 4 + 2][a_row] = av.z;
        As[a_k4 * 4 + 3][a_row] = av.w;
        float4 bv = *(const float4*)&B[(k0 + b_k) * N + n0 + b_j4 * 4];
        if (NORMB) {
            const int c = k0 + b_k;               // channel
            const int g = c >> 5;
            const float rs = stats[2 * g + 1];
            const float ga = gamma[c] * rs;
            const float be = fmaf(-stats[2 * g], ga, beta[c]);
            bv.x = fmaf(bv.x, ga, be);
            bv.y = fmaf(bv.y, ga, be);
            bv.z = fmaf(bv.z, ga, be);
            bv.w = fmaf(bv.w, ga, be);
        }
        *(float4*)&Bs[b_k][b_j4 * 4] = bv;
        __syncthreads();
#pragma unroll
        for (int kk = 0; kk < 16; kk++) {
            ulonglong2 a2 = *(const ulonglong2*)&As[kk][ty * 4]; // row pairs
            float4 b = *(const float4*)&Bs[kk][tx * 4];
            const u64 b0 = pack2(b.x, b.x);
            const u64 b1 = pack2(b.y, b.y);
            const u64 b2 = pack2(b.z, b.z);
            const u64 b3 = pack2(b.w, b.w);
            acc2[0][0] = fma2(a2.x, b0, acc2[0][0]);
            acc2[0][1] = fma2(a2.x, b1, acc2[0][1]);
            acc2[0][2] = fma2(a2.x, b2, acc2[0][2]);
            acc2[0][3] = fma2(a2.x, b3, acc2[0][3]);
            acc2[1][0] = fma2(a2.y, b0, acc2[1][0]);
            acc2[1][1] = fma2(a2.y, b1, acc2[1][1]);
            acc2[1][2] = fma2(a2.y, b2, acc2[1][2]);
            acc2[1][3] = fma2(a2.y, b3, acc2[1][3]);
        }
    }

    float accs[4][4];
#pragma unroll
    for (int i2 = 0; i2 < 2; i2++)
#pragma unroll
        for (int j = 0; j < 4; j++) {
            float2 v = unpack2(acc2[i2][j]);
            accs[2 * i2][j]     = v.x;
            accs[2 * i2 + 1][j] = v.y;
        }

#pragma unroll
    for (int i = 0; i < 4; i++) {
        const int m = m0 + ty * 4 + i;
        const float bs = bias[m];
        float4 o;
        o.x = accs[i][0] + bs;
        o.y = accs[i][1] + bs;
        o.z = accs[i][2] + bs;
        o.w = accs[i][3] + bs;
        const long ofs = (long)m * N + n0 + tx * 4;
        if (RESID) {
            float4 r = *(const float4*)&resid[ofs];
            o.x += r.x; o.y += r.y; o.z += r.z; o.w += r.w;
        }
        *(float4*)&C[ofs] = o;
    }
}

// ---------------------------------------------------------------------------
// 3. Flash attention, packed f32x2 with pair-packed exp2.
//    grid (64, 8): 64 query blocks (BM=64) x 8 heads, 64 thr/block, one thread
//    per query row. K/V tiles BN=32 transposed [jj][d], XOR-swizzled 16B
//    chunks (compute LDS.128 broadcast, STS conflict-free). Softmax in base-2
//    (scale*log2e folded into q). Next tile prefetched into registers.
//    Max and l reductions are tree/split to shorten dependency chains
//    (occupancy here is ~2.5 warps/SMSP — latency is only partly hidden).
// ---------------------------------------------------------------------------
__global__ __launch_bounds__(64) void attn_kernel(
    const float* __restrict__ qkv, float* __restrict__ ao) {
    __shared__ float4 Ks4[32 * 8];   // [jj][chunk ^ (jj&7)]
    __shared__ float4 Vs4[32 * 8];

    const int tid  = threadIdx.x;
    const int lane = tid & 31;
    const int half = tid >> 5;       // warp0 loads K, warp1 loads V
    const int h  = blockIdx.y;
    const int i  = blockIdx.x * 64 + tid;

    const float* qg = qkv + (h * DHEAD) * N_TOK;
    const float* kg = qkv + (INNER + h * DHEAD) * N_TOK;
    const float* vg = qkv + (2 * INNER + h * DHEAD) * N_TOK;
    const float* src = half ? vg : kg;
    float4* dst4 = half ? Vs4 : Ks4;

    // q pre-scaled into log2 domain: 1/sqrt(32) * log2(e)
    const float scale = 0.2550348653f;
    u64 q2[16];
#pragma unroll
    for (int d2 = 0; d2 < 16; d2++)
        q2[d2] = pack2(qg[(2 * d2) * N_TOK + i] * scale,
                       qg[(2 * d2 + 1) * N_TOK + i] * scale);

    u64 acc2[16];
#pragma unroll
    for (int d2 = 0; d2 < 16; d2++) acc2[d2] = 0ull;
    float m = -1e30f, l = 0.f;

    // hoisted packed constants for pair exp2
    const u64 MAG2 = pack2(12582912.f, 12582912.f);
    const u64 NMAG2 = pack2(-12582912.f, -12582912.f);
    const u64 C5 = pack2(1.3333558146428443e-3f, 1.3333558146428443e-3f);
    const u64 C4 = pack2(9.6181291076284771e-3f, 9.6181291076284771e-3f);
    const u64 C3 = pack2(5.5504108664798463e-2f, 5.5504108664798463e-2f);
    const u64 C2 = pack2(2.4022650695910071e-1f, 2.4022650695910071e-1f);
    const u64 C1 = pack2(6.9314718055994531e-1f, 6.9314718055994531e-1f);
    const u64 C0 = pack2(1.0f, 1.0f);

    // register prefetch buffer for next K/V tile
    float4 pf[8];
#pragma unroll
    for (int d4 = 0; d4 < 8; d4++) {
        pf[d4].x = src[(d4 * 4 + 0) * N_TOK + lane];
        pf[d4].y = src[(d4 * 4 + 1) * N_TOK + lane];
        pf[d4].z = src[(d4 * 4 + 2) * N_TOK + lane];
        pf[d4].w = src[(d4 * 4 + 3) * N_TOK + lane];
    }

    for (int j0 = 0; j0 < N_TOK; j0 += 32) {
        __syncthreads();
#pragma unroll
        for (int d4 = 0; d4 < 8; d4++)
            dst4[lane * 8 + (d4 ^ (lane & 7))] = pf[d4];
        __syncthreads();

        if (j0 + 32 < N_TOK) {   // prefetch next tile during compute
            const int jn = j0 + 32 + lane;
#pragma unroll
            for (int d4 = 0; d4 < 8; d4++) {
                pf[d4].x = src[(d4 * 4 + 0) * N_TOK + jn];
                pf[d4].y = src[(d4 * 4 + 1) * N_TOK + jn];
                pf[d4].z = src[(d4 * 4 + 2) * N_TOK + jn];
                pf[d4].w = src[(d4 * 4 + 3) * N_TOK + jn];
            }
        }

        // ---- scores (log2 domain), packed FFMA2, single chain per key ----
        float s[32];
#pragma unroll
        for (int jj = 0; jj < 32; jj++) {
            u64 a0 = 0ull;
#pragma unroll
            for (int d4 = 0; d4 < 8; d4++) {
                ulonglong2 kv = *(const ulonglong2*)&Ks4[jj * 8 + (d4 ^ (jj & 7))];
                a0 = fma2(q2[2 * d4],     kv.x, a0);
                a0 = fma2(q2[2 * d4 + 1], kv.y, a0);
            }
            float2 f0 = unpack2(a0);
            s[jj] = f0.x + f0.y;
        }

        // ---- online softmax update (tree max: dep depth 5, not 32) ----
        float mx[16];
#pragma unroll
        for (int jj = 0; jj < 16; jj++) mx[jj] = fmaxf(s[jj], s[jj + 16]);
#pragma unroll
        for (int jj = 0; jj < 8; jj++) mx[jj] = fmaxf(mx[jj], mx[jj + 8]);
#pragma unroll
        for (int jj = 0; jj < 4; jj++) mx[jj] = fmaxf(mx[jj], mx[jj + 4]);
        const float mt = fmaxf(fmaxf(fmaxf(mx[0], mx[2]),
                                     fmaxf(mx[1], mx[3])), m);
        const float resc = fast_exp2(m - mt);
        m = mt;
        l *= resc;
        const u64 rr = pack2(resc, resc);
#pragma unroll
        for (int d2 = 0; d2 < 16; d2++) acc2[d2] = mul2(acc2[d2], rr);

        // ---- pair-packed exp2 + PV accumulate (split l chains) ----
        float l0 = 0.f, l1 = 0.f;
#pragma unroll
        for (int jp = 0; jp < 16; jp++) {
            float y0 = fmaxf(s[2 * jp]     - m, -126.f);
            float y1 = fmaxf(s[2 * jp + 1] - m, -126.f);
            u64 y = pack2(y0, y1);
            u64 t = add2(y, MAG2);                      // packed round-to-int
            u64 u = add2(t, NMAG2);                     // integer part as float
            u64 f = add2(y, u ^ 0x8000000080000000ull); // frac = y - u
            u64 p = fma2(C5, f, C4);
            p = fma2(p, f, C3);
            p = fma2(p, f, C2);
            p = fma2(p, f, C1);
            p = fma2(p, f, C0);
            // per-half exponent splice
            float2 tb = unpack2(t);
            float2 pb = unpack2(p);
            float p0 = __int_as_float(__float_as_int(pb.x) +
                                      (__float_as_int(tb.x) << 23));
            float p1 = __int_as_float(__float_as_int(pb.y) +
                                      (__float_as_int(tb.y) << 23));
            l0 += p0;
            l1 += p1;
            const u64 pp0 = pack2(p0, p0);
            const u64 pp1 = pack2(p1, p1);
#pragma unroll
            for (int d4 = 0; d4 < 8; d4++) {
                ulonglong2 v0 = *(const ulonglong2*)&Vs4[(2 * jp) * 8 + (d4 ^ ((2 * jp) & 7))];
                acc2[2 * d4]     = fma2(pp0, v0.x, acc2[2 * d4]);
                acc2[2 * d4 + 1] = fma2(pp0, v0.y, acc2[2 * d4 + 1]);
            }
#pragma unroll
            for (int d4 = 0; d4 < 8; d4++) {
                ulonglong2 v1 = *(const ulonglong2*)&Vs4[(2 * jp + 1) * 8 + (d4 ^ ((2 * jp + 1) & 7))];
                acc2[2 * d4]     = fma2(pp1, v1.x, acc2[2 * d4]);
                acc2[2 * d4 + 1] = fma2(pp1, v1.y, acc2[2 * d4 + 1]);
            }
        }
        l += l0 + l1;
    }

    const float inv = 1.f / l;
#pragma unroll
    for (int d2 = 0; d2 < 16; d2++) {
        float2 v = unpack2(acc2[d2]);
        ao[(h * DHEAD + 2 * d2) * N_TOK + i]     = v.x * inv;
        ao[(h * DHEAD + 2 * d2 + 1) * N_TOK + i] = v.y * inv;
    }
}

// ---------------------------------------------------------------------------
extern "C" void kernel_launch(void* const* d_in, const int* in_sizes, int n_in,
                              void* d_out, int out_size) {
    const float* x     = (const float*)d_in[0];
    const float* gamma = (const float*)d_in[1];
    const float* beta  = (const float*)d_in[2];
    const float* w_qkv = (const float*)d_in[3];
    const float* b_qkv = (const float*)d_in[4];
    const float* w_out = (const float*)d_in[5];
    const float* b_out = (const float*)d_in[6];
    float* out = (float*)d_out;

    float *qkv, *ao, *stats;
    cudaGetSymbolAddress((void**)&qkv,   g_qkv);
    cudaGetSymbolAddress((void**)&ao,    g_ao);
    cudaGetSymbolAddress((void**)&stats, g_stats);

    gn_stats_kernel<<<8, 256>>>(x, stats);
    // QKV projection with GroupNorm fused into the B-tile load
    gemm_kernel<false, true><<<dim3(64, 12), 256>>>(
        w_qkv, x, b_qkv, nullptr, gamma, beta, stats, qkv,
        3 * INNER, N_TOK, C_DIM);
    attn_kernel<<<dim3(64, 8), 64>>>(qkv, ao);
    gemm_kernel<true, false><<<dim3(64, 4), 256>>>(
        w_out, ao, b_out, x, nullptr, nullptr, nullptr, out,
        C_DIM, N_TOK, INNER);
}

// round 14
// speedup vs baseline: 1.0885x; 1.0885x over previous
#include <cuda_runtime.h>
#include <cuda_bf16.h>

// SelfAttention3D — GroupNorm(8 groups) -> QKV proj -> 8-head attention
// (dhead=32, n=4096) -> out proj + residual.  b=1, c=256.
//
// Pipeline (5 launches, graph-capturable, scratch in __device__ globals):
//   1. gn_stats      : per-group mean / rsqrt(var+eps)
//   2. gemm<NORMB>   : qkv = w_qkv @ groupnorm(x) + b_qkv   -> g_qkv [768][4096]
//   3. attn (split-K): flash-attention partials, 8 key-splits -> g_pacc/g_pml
//                      (R11 ncu: chip was grid-starved at 221 thr/SM; split-K
//                       raises resident warps to the reg-file cap)
//   4. combine       : merge 8 partial softmaxes               -> g_ao
//   5. gemm+resid    : out = w_out @ ao + b_out + x            -> d_out

#define N_TOK 4096
#define C_DIM 256
#define INNER 256
#define HEADS 8
#define DHEAD 32
#define NSPLIT 8
#define KEYS_PER_SPLIT (N_TOK / NSPLIT)   // 512

__device__ float g_qkv[3 * INNER * N_TOK];
__device__ float g_ao[INNER * N_TOK];
__device__ float g_stats[16];
__device__ float g_pacc[NSPLIT * HEADS * DHEAD * N_TOK];  // 33.5 MB partial acc
__device__ float g_pml[2 * NSPLIT * HEADS * N_TOK];       // m / l partials

typedef unsigned long long u64;

// ---------------------------------------------------------------------------
// Packed f32x2 helpers (sm_103a FFMA2 path — only reachable via PTX).
// ---------------------------------------------------------------------------
__device__ __forceinline__ u64 fma2(u64 a, u64 b, u64 c) {
    u64 d;
    asm("fma.rn.f32x2 %0, %1, %2, %3;" : "=l"(d) : "l"(a), "l"(b), "l"(c));
    return d;
}
__device__ __forceinline__ u64 add2(u64 a, u64 b) {
    u64 d;
    asm("add.rn.f32x2 %0, %1, %2;" : "=l"(d) : "l"(a), "l"(b));
    return d;
}
__device__ __forceinline__ u64 mul2(u64 a, u64 b) {
    u64 d;
    asm("mul.rn.f32x2 %0, %1, %2;" : "=l"(d) : "l"(a), "l"(b));
    return d;
}
__device__ __forceinline__ u64 pack2(float lo, float hi) {
    u64 d;
    unsigned l = __float_as_uint(lo), h = __float_as_uint(hi);
    asm("mov.b64 %0, {%1, %2};" : "=l"(d) : "r"(l), "r"(h));
    return d;
}
__device__ __forceinline__ float2 unpack2(u64 v) {
    unsigned l, h;
    asm("mov.b64 {%0, %1}, %2;" : "=r"(l), "=r"(h) : "l"(v));
    return make_float2(__uint_as_float(l), __uint_as_float(h));
}

// ---------------------------------------------------------------------------
// FFMA/ALU-only exp2 (scalar): magic-number round, degree-5 poly on [-.5,.5]
// (rel err ~2.4e-6), exponent splice via (bits(t)<<23). Keeps MUFU idle.
// ---------------------------------------------------------------------------
__device__ __forceinline__ float fast_exp2(float y) {
    y = fmaxf(y, -126.0f);
    float t = y + 12582912.0f;
    float f = y - (t - 12582912.0f);
    float p = 1.3333558146428443e-3f;
    p = fmaf(p, f, 9.6181291076284771e-3f);
    p = fmaf(p, f, 5.5504108664798463e-2f);
    p = fmaf(p, f, 2.4022650695910071e-1f);
    p = fmaf(p, f, 6.9314718055994531e-1f);
    p = fmaf(p, f, 1.0f);
    return __int_as_float(__float_as_int(p) + (__float_as_int(t) << 23));
}

// ---------------------------------------------------------------------------
// 1. GroupNorm statistics: one block per group (32 ch x 4096 elems)
// ---------------------------------------------------------------------------
__global__ __launch_bounds__(256) void gn_stats_kernel(
    const float* __restrict__ x, float* __restrict__ stats) {
    __shared__ float sh[512];
    const int g = blockIdx.x, tid = threadIdx.x;
    const float4* x4 = (const float4*)(x + g * 32 * N_TOK);
    float s = 0.f, s2 = 0.f;
    for (int i = tid; i < 32768; i += 256) {
        float4 v = x4[i];
        s  += (v.x + v.y) + (v.z + v.w);
        s2 += (v.x * v.x + v.y * v.y) + (v.z * v.z + v.w * v.w);
    }
    sh[tid] = s; sh[256 + tid] = s2;
    __syncthreads();
    for (int off = 128; off >= 32; off >>= 1) {
        if (tid < off) { sh[tid] += sh[tid + off]; sh[256 + tid] += sh[256 + tid + off]; }
        __syncthreads();
    }
    if (tid < 32) {
        float a = sh[tid], b = sh[256 + tid];
#pragma unroll
        for (int off = 16; off > 0; off >>= 1) {
            a += __shfl_down_sync(0xffffffffu, a, off);
            b += __shfl_down_sync(0xffffffffu, b, off);
        }
        if (tid == 0) {
            const float inv_n = 1.f / 131072.f;
            float mu  = a * inv_n;
            float var = b * inv_n - mu * mu;
            stats[2 * g]     = mu;
            stats[2 * g + 1] = rsqrtf(var + 1e-5f);
        }
    }
}

// ---------------------------------------------------------------------------
// 2/5. SGEMM, f32x2 inner loop (unchanged from R11 PASS).
// ---------------------------------------------------------------------------
template <bool RESID, bool NORMB>
__global__ __launch_bounds__(256) void gemm_kernel(
    const float* __restrict__ A, const float* __restrict__ B,
    const float* __restrict__ bias, const float* __restrict__ resid,
    const float* __restrict__ gamma, const float* __restrict__ beta,
    const float* __restrict__ stats,
    float* __restrict__ C, int M, int N, int K) {
    __shared__ __align__(16) float As[16][68];
    __shared__ __align__(16) float Bs[16][64];

    const int tid = threadIdx.x;
    const int m0 = blockIdx.y * 64;
    const int n0 = blockIdx.x * 64;
    const int ty = tid >> 4, tx = tid & 15;

    const int a_row = tid >> 2;
    const int a_k4  = tid & 3;
    const int b_k   = tid >> 4;
    const int b_j4  = tid & 15;

    u64 acc2[2][4];
#pragma unroll
    for (int i = 0; i < 2; i++)
#pragma unroll
        for (int j = 0; j < 4; j++) acc2[i][j] = 0ull;

    for (int k0 = 0; k0 < K; k0 += 16) {
        __syncthreads();
        float4 av = *(const float4*)&A[(m0 + a_row) * K + k0 + a_k4 * 4];
        As[a_k4 * 4 + 0][a_row] = av.x;
        As[a_k4 * 4 + 1][a_row] = av.y;
        As[a_k4 * 4 + 2][a_row] = av.z;
        As[a_k4 * 4 + 3][a_row] = av.w;
        float4 bv = *(const float4*)&B[(k0 + b_k) * N + n0 + b_j4 * 4];
        if (NORMB) {
            const int c = k0 + b_k;
            const int g = c >> 5;
            const float rs = stats[2 * g + 1];
            const float ga = gamma[c] * rs;
            const float be = fmaf(-stats[2 * g], ga, beta[c]);
            bv.x = fmaf(bv.x, ga, be);
            bv.y = fmaf(bv.y, ga, be);
            bv.z = fmaf(bv.z, ga, be);
            bv.w = fmaf(bv.w, ga, be);
        }
        *(float4*)&Bs[b_k][b_j4 * 4] = bv;
        __syncthreads();
#pragma unroll
        for (int kk = 0; kk < 16; kk++) {
            ulonglong2 a2 = *(const ulonglong2*)&As[kk][ty * 4];
            float4 b = *(const float4*)&Bs[kk][tx * 4];
            const u64 b0 = pack2(b.x, b.x);
            const u64 b1 = pack2(b.y, b.y);
            const u64 b2 = pack2(b.z, b.z);
            const u64 b3 = pack2(b.w, b.w);
            acc2[0][0] = fma2(a2.x, b0, acc2[0][0]);
            acc2[0][1] = fma2(a2.x, b1, acc2[0][1]);
            acc2[0][2] = fma2(a2.x, b2, acc2[0][2]);
            acc2[0][3] = fma2(a2.x, b3, acc2[0][3]);
            acc2[1][0] = fma2(a2.y, b0, acc2[1][0]);
            acc2[1][1] = fma2(a2.y, b1, acc2[1][1]);
            acc2[1][2] = fma2(a2.y, b2, acc2[1][2]);
            acc2[1][3] = fma2(a2.y, b3, acc2[1][3]);
        }
    }

    float accs[4][4];
#pragma unroll
    for (int i2 = 0; i2 < 2; i2++)
#pragma unroll
        for (int j = 0; j < 4; j++) {
            float2 v = unpack2(acc2[i2][j]);
            accs[2 * i2][j]     = v.x;
            accs[2 * i2 + 1][j] = v.y;
        }

#pragma unroll
    for (int i = 0; i < 4; i++) {
        const int m = m0 + ty * 4 + i;
        const float bs = bias[m];
        float4 o;
        o.x = accs[i][0] + bs;
        o.y = accs[i][1] + bs;
        o.z = accs[i][2] + bs;
        o.w = accs[i][3] + bs;
        const long ofs = (long)m * N + n0 + tx * 4;
        if (RESID) {
            float4 r = *(const float4*)&resid[ofs];
            o.x += r.x; o.y += r.y; o.z += r.z; o.w += r.w;
        }
        *(float4*)&C[ofs] = o;
    }
}

// ---------------------------------------------------------------------------
// 3. Flash attention partials, split-K.
//    grid (64, 8, NSPLIT): query block x head x key-split. 64 thr/block, one
//    thread per query row; each split covers 512 keys (16 tiles of 32).
//    Emits unnormalized (m, l, acc[32]) per (row, head, split).
//    Inner loops identical to the R11 PASS kernel.
// ---------------------------------------------------------------------------
__global__ __launch_bounds__(64) void attn_kernel(
    const float* __restrict__ qkv,
    float* __restrict__ pacc, float* __restrict__ pml) {
    __shared__ float4 Ks4[32 * 8];   // [jj][chunk ^ (jj&7)]
    __shared__ float4 Vs4[32 * 8];

    const int tid  = threadIdx.x;
    const int lane = tid & 31;
    const int half = tid >> 5;       // warp0 loads K, warp1 loads V
    const int h  = blockIdx.y;
    const int sp = blockIdx.z;
    const int i  = blockIdx.x * 64 + tid;
    const int jbase = sp * KEYS_PER_SPLIT;

    const float* qg = qkv + (h * DHEAD) * N_TOK;
    const float* kg = qkv + (INNER + h * DHEAD) * N_TOK;
    const float* vg = qkv + (2 * INNER + h * DHEAD) * N_TOK;
    const float* src = half ? vg : kg;
    float4* dst4 = half ? Vs4 : Ks4;

    // q pre-scaled into log2 domain: 1/sqrt(32) * log2(e)
    const float scale = 0.2550348653f;
    u64 q2[16];
#pragma unroll
    for (int d2 = 0; d2 < 16; d2++)
        q2[d2] = pack2(qg[(2 * d2) * N_TOK + i] * scale,
                       qg[(2 * d2 + 1) * N_TOK + i] * scale);

    u64 acc2[16];
#pragma unroll
    for (int d2 = 0; d2 < 16; d2++) acc2[d2] = 0ull;
    float m = -1e30f, l = 0.f;

    const u64 MAG2 = pack2(12582912.f, 12582912.f);
    const u64 NMAG2 = pack2(-12582912.f, -12582912.f);
    const u64 C5 = pack2(1.3333558146428443e-3f, 1.3333558146428443e-3f);
    const u64 C4 = pack2(9.6181291076284771e-3f, 9.6181291076284771e-3f);
    const u64 C3 = pack2(5.5504108664798463e-2f, 5.5504108664798463e-2f);
    const u64 C2 = pack2(2.4022650695910071e-1f, 2.4022650695910071e-1f);
    const u64 C1 = pack2(6.9314718055994531e-1f, 6.9314718055994531e-1f);
    const u64 C0 = pack2(1.0f, 1.0f);

    // register prefetch buffer for next K/V tile
    float4 pf[8];
#pragma unroll
    for (int d4 = 0; d4 < 8; d4++) {
        pf[d4].x = src[(d4 * 4 + 0) * N_TOK + jbase + lane];
        pf[d4].y = src[(d4 * 4 + 1) * N_TOK + jbase + lane];
        pf[d4].z = src[(d4 * 4 + 2) * N_TOK + jbase + lane];
        pf[d4].w = src[(d4 * 4 + 3) * N_TOK + jbase + lane];
    }

    for (int j0 = jbase; j0 < jbase + KEYS_PER_SPLIT; j0 += 32) {
        __syncthreads();
#pragma unroll
        for (int d4 = 0; d4 < 8; d4++)
            dst4[lane * 8 + (d4 ^ (lane & 7))] = pf[d4];
        __syncthreads();

        if (j0 + 32 < jbase + KEYS_PER_SPLIT) {
            const int jn = j0 + 32 + lane;
#pragma unroll
            for (int d4 = 0; d4 < 8; d4++) {
                pf[d4].x = src[(d4 * 4 + 0) * N_TOK + jn];
                pf[d4].y = src[(d4 * 4 + 1) * N_TOK + jn];
                pf[d4].z = src[(d4 * 4 + 2) * N_TOK + jn];
                pf[d4].w = src[(d4 * 4 + 3) * N_TOK + jn];
            }
        }

        // ---- scores (log2 domain), packed FFMA2 ----
        float s[32];
#pragma unroll
        for (int jj = 0; jj < 32; jj++) {
            u64 a0 = 0ull;
#pragma unroll
            for (int d4 = 0; d4 < 8; d4++) {
                ulonglong2 kv = *(const ulonglong2*)&Ks4[jj * 8 + (d4 ^ (jj & 7))];
                a0 = fma2(q2[2 * d4],     kv.x, a0);
                a0 = fma2(q2[2 * d4 + 1], kv.y, a0);
            }
            float2 f0 = unpack2(a0);
            s[jj] = f0.x + f0.y;
        }

        // ---- online softmax update (tree max) ----
        float mx[16];
#pragma unroll
        for (int jj = 0; jj < 16; jj++) mx[jj] = fmaxf(s[jj], s[jj + 16]);
#pragma unroll
        for (int jj = 0; jj < 8; jj++) mx[jj] = fmaxf(mx[jj], mx[jj + 8]);
#pragma unroll
        for (int jj = 0; jj < 4; jj++) mx[jj] = fmaxf(mx[jj], mx[jj + 4]);
        const float mt = fmaxf(fmaxf(fmaxf(mx[0], mx[2]),
                                     fmaxf(mx[1], mx[3])), m);
        const float resc = fast_exp2(m - mt);
        m = mt;
        l *= resc;
        const u64 rr = pack2(resc, resc);
#pragma unroll
        for (int d2 = 0; d2 < 16; d2++) acc2[d2] = mul2(acc2[d2], rr);

        // ---- pair-packed exp2 + PV accumulate (split l chains) ----
        float l0 = 0.f, l1 = 0.f;
#pragma unroll
        for (int jp = 0; jp < 16; jp++) {
            float y0 = fmaxf(s[2 * jp]     - m, -126.f);
            float y1 = fmaxf(s[2 * jp + 1] - m, -126.f);
            u64 y = pack2(y0, y1);
            u64 t = add2(y, MAG2);
            u64 u = add2(t, NMAG2);
            u64 f = add2(y, u ^ 0x8000000080000000ull);
            u64 p = fma2(C5, f, C4);
            p = fma2(p, f, C3);
            p = fma2(p, f, C2);
            p = fma2(p, f, C1);
            p = fma2(p, f, C0);
            float2 tb = unpack2(t);
            float2 pb = unpack2(p);
            float p0 = __int_as_float(__float_as_int(pb.x) +
                                      (__float_as_int(tb.x) << 23));
            float p1 = __int_as_float(__float_as_int(pb.y) +
                                      (__float_as_int(tb.y) << 23));
            l0 += p0;
            l1 += p1;
            const u64 pp0 = pack2(p0, p0);
            const u64 pp1 = pack2(p1, p1);
#pragma unroll
            for (int d4 = 0; d4 < 8; d4++) {
                ulonglong2 v0 = *(const ulonglong2*)&Vs4[(2 * jp) * 8 + (d4 ^ ((2 * jp) & 7))];
                acc2[2 * d4]     = fma2(pp0, v0.x, acc2[2 * d4]);
                acc2[2 * d4 + 1] = fma2(pp0, v0.y, acc2[2 * d4 + 1]);
            }
#pragma unroll
            for (int d4 = 0; d4 < 8; d4++) {
                ulonglong2 v1 = *(const ulonglong2*)&Vs4[(2 * jp + 1) * 8 + (d4 ^ ((2 * jp + 1) & 7))];
                acc2[2 * d4]     = fma2(pp1, v1.x, acc2[2 * d4]);
                acc2[2 * d4 + 1] = fma2(pp1, v1.y, acc2[2 * d4 + 1]);
            }
        }
        l += l0 + l1;
    }

    // unnormalized partial out + (m, l)
#pragma unroll
    for (int d2 = 0; d2 < 16; d2++) {
        float2 v = unpack2(acc2[d2]);
        pacc[(((sp * HEADS + h) * DHEAD + 2 * d2) * N_TOK) + i]     = v.x;
        pacc[(((sp * HEADS + h) * DHEAD + 2 * d2 + 1) * N_TOK) + i] = v.y;
    }
    pml[((0 * NSPLIT + sp) * HEADS + h) * N_TOK + i] = m;
    pml[((1 * NSPLIT + sp) * HEADS + h) * N_TOK + i] = l;
}

// ---------------------------------------------------------------------------
// 4. Combine split-K partials. grid (16, 8, 4): i-block x head x d-group(8).
//    out[d] = Σ_s acc_s[d]·2^(m_s−M) / Σ_s l_s·2^(m_s−M).  Coalesced along i.
// ---------------------------------------------------------------------------
__global__ __launch_bounds__(256) void combine_kernel(
    const float* __restrict__ pacc, const float* __restrict__ pml,
    float* __restrict__ ao) {
    const int i = blockIdx.x * 256 + threadIdx.x;
    const int h = blockIdx.y;
    const int d0 = blockIdx.z * 8;

    float ms[NSPLIT], ls[NSPLIT];
#pragma unroll
    for (int s = 0; s < NSPLIT; s++) {
        ms[s] = pml[((0 * NSPLIT + s) * HEADS + h) * N_TOK + i];
        ls[s] = pml[((1 * NSPLIT + s) * HEADS + h) * N_TOK + i];
    }
    float M = ms[0];
#pragma unroll
    for (int s = 1; s < NSPLIT; s++) M = fmaxf(M, ms[s]);
    float w[NSPLIT], L = 0.f;
#pragma unroll
    for (int s = 0; s < NSPLIT; s++) {
        w[s] = fast_exp2(ms[s] - M);
        L = fmaf(ls[s], w[s], L);
    }
    const float inv = 1.f / L;
#pragma unroll
    for (int dd = 0; dd < 8; dd++) {
        const int d = d0 + dd;
        float acc = 0.f;
#pragma unroll
        for (int s = 0; s < NSPLIT; s++)
            acc = fmaf(pacc[(((s * HEADS + h) * DHEAD + d) * N_TOK) + i],
                       w[s], acc);
        ao[(h * DHEAD + d) * N_TOK + i] = acc * inv;
    }
}

// ---------------------------------------------------------------------------
extern "C" void kernel_launch(void* const* d_in, const int* in_sizes, int n_in,
                              void* d_out, int out_size) {
    const float* x     = (const float*)d_in[0];
    const float* gamma = (const float*)d_in[1];
    const float* beta  = (const float*)d_in[2];
    const float* w_qkv = (const float*)d_in[3];
    const float* b_qkv = (const float*)d_in[4];
    const float* w_out = (const float*)d_in[5];
    const float* b_out = (const float*)d_in[6];
    float* out = (float*)d_out;

    float *qkv, *ao, *stats, *pacc, *pml;
    cudaGetSymbolAddress((void**)&qkv,   g_qkv);
    cudaGetSymbolAddress((void**)&ao,    g_ao);
    cudaGetSymbolAddress((void**)&stats, g_stats);
    cudaGetSymbolAddress((void**)&pacc,  g_pacc);
    cudaGetSymbolAddress((void**)&pml,   g_pml);

    gn_stats_kernel<<<8, 256>>>(x, stats);
    gemm_kernel<false, true><<<dim3(64, 12), 256>>>(
        w_qkv, x, b_qkv, nullptr, gamma, beta, stats, qkv,
        3 * INNER, N_TOK, C_DIM);
    attn_kernel<<<dim3(64, HEADS, NSPLIT), 64>>>(qkv, pacc, pml);
    combine_kernel<<<dim3(N_TOK / 256, HEADS, 4), 256>>>(pacc, pml, ao);
    gemm_kernel<true, false><<<dim3(64, 4), 256>>>(
        w_out, ao, b_out, x, nullptr, nullptr, nullptr, out,
        C_DIM, N_TOK, INNER);
}